// round 2
// baseline (speedup 1.0000x reference)
#include <cuda_runtime.h>
#include <cuda_bf16.h>

// Problem dims
#define T_DIM 512
#define B_DIM 32
#define I_DIM 512
#define H_DIM 512
#define G_DIM 2048            // 4*H
#define S_TBH (T_DIM*B_DIM*H_DIM)   // 8388608, one [T,B,H] slab

// Scratch: pre-activations for one layer [T, B, 4H] (reused across layers)
__device__ float g_pre[(size_t)T_DIM * B_DIM * G_DIM];

// Grid-barrier state (monotonic across graph replays)
__device__ unsigned gSub[8 * 32];   // 8 striped sub-counters (128B apart)
__device__ unsigned gMaster;
__device__ unsigned gGen;

// ---------------------------------------------------------------------------
// GEMM: pre[M,N] = A[M,K] @ W[N,K]^T + bih[N] + bhh[N]
// M = T*B = 16384, N = 2048, K = 512. fp32, 128x128 tile, 8x8 per thread.
// ---------------------------------------------------------------------------
__global__ __launch_bounds__(256) void gemm_pre_kernel(
    const float* __restrict__ A,
    const float* __restrict__ W,
    const float* __restrict__ bih,
    const float* __restrict__ bhh,
    float* __restrict__ C)
{
    const int K = I_DIM;      // 512
    const int N = G_DIM;      // 2048

    __shared__ float As[8][128];
    __shared__ float Bs[8][128];

    const int bm = blockIdx.y * 128;
    const int bn = blockIdx.x * 128;
    const int tid = threadIdx.x;
    const int tx = tid & 15;        // 0..15 -> col frag
    const int ty = tid >> 4;        // 0..15 -> row frag

    float acc[8][8];
#pragma unroll
    for (int i = 0; i < 8; i++)
#pragma unroll
        for (int j = 0; j < 8; j++) acc[i][j] = 0.f;

    const int lr = tid >> 1;            // 0..127
    const int lc = (tid & 1) * 4;       // 0 or 4
    const float* Aptr = A + (size_t)(bm + lr) * K + lc;
    const float* Wptr = W + (size_t)(bn + lr) * K + lc;

    for (int k0 = 0; k0 < K; k0 += 8) {
        float4 av = *(const float4*)(Aptr + k0);
        float4 wv = *(const float4*)(Wptr + k0);
        __syncthreads();
        As[lc + 0][lr] = av.x; As[lc + 1][lr] = av.y;
        As[lc + 2][lr] = av.z; As[lc + 3][lr] = av.w;
        Bs[lc + 0][lr] = wv.x; Bs[lc + 1][lr] = wv.y;
        Bs[lc + 2][lr] = wv.z; Bs[lc + 3][lr] = wv.w;
        __syncthreads();
#pragma unroll
        for (int kk = 0; kk < 8; kk++) {
            float a[8], b[8];
            *(float4*)(a)     = *(const float4*)&As[kk][ty * 8];
            *(float4*)(a + 4) = *(const float4*)&As[kk][ty * 8 + 4];
            *(float4*)(b)     = *(const float4*)&Bs[kk][tx * 8];
            *(float4*)(b + 4) = *(const float4*)&Bs[kk][tx * 8 + 4];
#pragma unroll
            for (int i = 0; i < 8; i++)
#pragma unroll
                for (int j = 0; j < 8; j++)
                    acc[i][j] = fmaf(a[i], b[j], acc[i][j]);
        }
    }

    float bias[8];
#pragma unroll
    for (int j = 0; j < 8; j++) {
        int col = bn + tx * 8 + j;
        bias[j] = bih[col] + bhh[col];
    }
#pragma unroll
    for (int i = 0; i < 8; i++) {
        int row = bm + ty * 8 + i;
        float* cp = C + (size_t)row * N + bn + tx * 8;
        float4 v0, v1;
        v0.x = acc[i][0] + bias[0]; v0.y = acc[i][1] + bias[1];
        v0.z = acc[i][2] + bias[2]; v0.w = acc[i][3] + bias[3];
        v1.x = acc[i][4] + bias[4]; v1.y = acc[i][5] + bias[5];
        v1.z = acc[i][6] + bias[6]; v1.w = acc[i][7] + bias[7];
        *(float4*)(cp)     = v0;
        *(float4*)(cp + 4) = v1;
    }
}

// ---------------------------------------------------------------------------
// Persistent LSTM recurrence for one layer.
// 128 CTAs x 256 threads. CTA bx owns h-units j0 = bx*4 .. bx*4+3
// (16 gate columns: gate*512 + j0 + jl). Whh slice cached in smem.
// Per step: gates = pre_t + h_{t-1} @ Whh^T ; pointwise ; write outputs ;
// 2-level grid barrier.
// ---------------------------------------------------------------------------
__global__ __launch_bounds__(256, 1) void lstm_recur_kernel(
    const float* __restrict__ pre,     // [T, B, 4H]
    const float* __restrict__ whh,     // [4H, H]
    float* __restrict__ out,           // full output base [6, L, T, B, H]
    int layer)
{
    extern __shared__ float4 dsm4[];
    float4* sh4 = dsm4;                         // [32][129] float4 (padded)
    float4* sW4 = dsm4 + 32 * 129;              // [16][128] float4
    float*  sg  = (float*)(sW4 + 16 * 128);     // [32][17]
    float*  sc  = sg + 32 * 17;                 // [128]
    __shared__ unsigned sBase;

    const int tid = threadIdx.x;
    const int bx  = blockIdx.x;
    const int j0  = bx * 4;

    float* out_h = out + (size_t)0 * 2 * S_TBH + (size_t)layer * S_TBH;
    float* out_c = out + (size_t)1 * 2 * S_TBH + (size_t)layer * S_TBH;
    float* out_i = out + (size_t)2 * 2 * S_TBH + (size_t)layer * S_TBH;
    float* out_f = out + (size_t)3 * 2 * S_TBH + (size_t)layer * S_TBH;
    float* out_g = out + (size_t)4 * 2 * S_TBH + (size_t)layer * S_TBH;
    float* out_o = out + (size_t)5 * 2 * S_TBH + (size_t)layer * S_TBH;

    if (tid == 0) sBase = *(volatile unsigned*)&gGen;

    // Load this CTA's 16 Whh rows (cidx = gate*4 + jl -> row gate*512+j0+jl)
    const float4* whh4 = (const float4*)whh;
#pragma unroll
    for (int i = 0; i < 8; i++) {
        int f = tid + i * 256;              // 0..2047
        int cidx = f >> 7, k4 = f & 127;
        int gate = cidx >> 2, jl = cidx & 3;
        int row = gate * 512 + j0 + jl;
        sW4[cidx * 128 + k4] = whh4[(size_t)row * 128 + k4];
    }
    if (tid < 128) sc[tid] = 0.f;
    __syncthreads();

    const int w    = tid >> 5;
    const int lane = tid & 31;
    const int b    = lane;
    const int cidx0 = 2 * w, cidx1 = 2 * w + 1;
    const int col0 = (cidx0 >> 2) * 512 + j0 + (cidx0 & 3);
    const int col1 = (cidx1 >> 2) * 512 + j0 + (cidx1 & 3);

    for (int t = 0; t < T_DIM; t++) {
        // stage h_{t-1} into smem (zeros at t=0)
        if (t == 0) {
#pragma unroll
            for (int i = 0; i < 16; i++) {
                int f = tid + i * 256;      // 0..4095
                int bb = f >> 7, k4 = f & 127;
                sh4[bb * 129 + k4] = make_float4(0.f, 0.f, 0.f, 0.f);
            }
        } else {
            const float4* hsrc = (const float4*)(out_h + (size_t)(t - 1) * (B_DIM * H_DIM));
#pragma unroll
            for (int i = 0; i < 16; i++) {
                int f = tid + i * 256;
                int bb = f >> 7, k4 = f & 127;
                sh4[bb * 129 + k4] = hsrc[f];
            }
        }
        float acc0 = pre[(size_t)t * (B_DIM * G_DIM) + b * G_DIM + col0];
        float acc1 = pre[(size_t)t * (B_DIM * G_DIM) + b * G_DIM + col1];
        __syncthreads();

        const float4* hrow = sh4 + b * 129;
        const float4* w0p  = sW4 + cidx0 * 128;
        const float4* w1p  = sW4 + cidx1 * 128;
#pragma unroll 4
        for (int k4 = 0; k4 < 128; k4++) {
            float4 hv = hrow[k4];
            float4 w0 = w0p[k4];
            float4 w1 = w1p[k4];
            acc0 = fmaf(hv.x, w0.x, acc0); acc0 = fmaf(hv.y, w0.y, acc0);
            acc0 = fmaf(hv.z, w0.z, acc0); acc0 = fmaf(hv.w, w0.w, acc0);
            acc1 = fmaf(hv.x, w1.x, acc1); acc1 = fmaf(hv.y, w1.y, acc1);
            acc1 = fmaf(hv.z, w1.z, acc1); acc1 = fmaf(hv.w, w1.w, acc1);
        }
        sg[b * 17 + cidx0] = acc0;
        sg[b * 17 + cidx1] = acc1;
        __syncthreads();

        if (tid < 128) {
            int eb = tid >> 2, jl = tid & 3;
            float xi = sg[eb * 17 + 0  + jl];
            float xf = sg[eb * 17 + 4  + jl];
            float xg = sg[eb * 17 + 8  + jl];
            float xo = sg[eb * 17 + 12 + jl];
            float it = 1.f / (1.f + __expf(-xi));
            float ft = 1.f / (1.f + __expf(-xf));
            float gt = tanhf(xg);
            float ot = 1.f / (1.f + __expf(-xo));
            float cold = sc[tid];
            float cnew = fmaf(ft, cold, it * gt);
            float hnew = ot * tanhf(cnew);
            sc[tid] = cnew;
            size_t idx = (size_t)t * (B_DIM * H_DIM) + eb * H_DIM + j0 + jl;
            out_h[idx] = hnew;
            out_c[idx] = cnew;
            out_i[idx] = it;
            out_f[idx] = ft;
            out_g[idx] = gt;
            out_o[idx] = ot;
        }

        if (t < T_DIM - 1) {
            __syncthreads();
            if (tid == 0) {
                __threadfence();
                unsigned v = atomicAdd(&gSub[(bx & 7) * 32], 1u) + 1u;
                if ((v & 15u) == 0u) {                    // 16 CTAs per sub
                    unsigned m = atomicAdd(&gMaster, 1u) + 1u;
                    if ((m & 7u) == 0u)                   // 8 subs
                        atomicAdd(&gGen, 1u);
                }
                unsigned target = sBase + (unsigned)(t + 1);
                unsigned g;
                do { g = *(volatile unsigned*)&gGen; } while ((int)(g - target) < 0);
                __threadfence();
            }
            __syncthreads();
        }
    }
}

// ---------------------------------------------------------------------------
extern "C" void kernel_launch(void* const* d_in, const int* in_sizes, int n_in,
                              void* d_out, int out_size)
{
    (void)in_sizes; (void)n_in; (void)out_size;
    const float* x    = (const float*)d_in[0];   // [T, B, I]
    const float* w_ih = (const float*)d_in[1];   // [L, 4H, I]
    const float* w_hh = (const float*)d_in[2];   // [L, 4H, H]
    const float* b_ih = (const float*)d_in[3];   // [L, 4H]
    const float* b_hh = (const float*)d_in[4];   // [L, 4H]
    float* out = (float*)d_out;                  // [6, L, T, B, H]

    float* pre;
    cudaGetSymbolAddress((void**)&pre, g_pre);

    const size_t recur_smem =
        (size_t)(32 * 129 + 16 * 128) * sizeof(float4) +
        (size_t)(32 * 17 + 128) * sizeof(float);
    cudaFuncSetAttribute(lstm_recur_kernel,
                         cudaFuncAttributeMaxDynamicSharedMemorySize,
                         (int)recur_smem);

    dim3 ggrid(G_DIM / 128, (T_DIM * B_DIM) / 128);   // 16 x 128

    // Layer 0
    gemm_pre_kernel<<<ggrid, 256>>>(x, w_ih, b_ih, b_hh, pre);
    lstm_recur_kernel<<<128, 256, recur_smem>>>(pre, w_hh, out, 0);

    // Layer 1: input is layer-0 h = out region (q=0, l=0)
    const float* x1 = out;   // offset 0
    gemm_pre_kernel<<<ggrid, 256>>>(x1,
                                    w_ih + (size_t)G_DIM * I_DIM,
                                    b_ih + G_DIM,
                                    b_hh + G_DIM,
                                    pre);
    lstm_recur_kernel<<<128, 256, recur_smem>>>(pre,
                                                w_hh + (size_t)G_DIM * H_DIM,
                                                out, 1);
}

// round 4
// speedup vs baseline: 1.3141x; 1.3141x over previous
#include <cuda_runtime.h>
#include <cuda_bf16.h>

typedef unsigned long long u64;

// Problem dims
#define T_DIM 512
#define B_DIM 32
#define I_DIM 512
#define H_DIM 512
#define G_DIM 2048            // 4*H
#define S_TBH (T_DIM*B_DIM*H_DIM)   // one [T,B,H] slab

// Scratch: pre-activations for one layer [T, B, 4H]
__device__ float g_pre[(size_t)T_DIM * B_DIM * G_DIM];

// Grid-barrier state (monotonic across graph replays)
__device__ unsigned gSub[8 * 32];
__device__ unsigned gMaster;
__device__ unsigned gGen;

// ---- f32x2 helpers (Blackwell packed fp32 pipe) -----------------------------
__device__ __forceinline__ u64 ffma2(u64 a, u64 b, u64 c) {
    u64 d; asm("fma.rn.f32x2 %0,%1,%2,%3;" : "=l"(d) : "l"(a), "l"(b), "l"(c));
    return d;
}
__device__ __forceinline__ u64 fsplat(float a) {
    u64 r; asm("mov.b64 %0,{%1,%1};" : "=l"(r) : "f"(a)); return r;
}
__device__ __forceinline__ u64 fpack(float lo, float hi) {
    u64 r; asm("mov.b64 %0,{%1,%2};" : "=l"(r) : "f"(lo), "f"(hi)); return r;
}
__device__ __forceinline__ float2 funpack(u64 v) {
    float lo, hi; asm("mov.b64 {%0,%1},%2;" : "=f"(lo), "=f"(hi) : "l"(v));
    return make_float2(lo, hi);
}

// ---------------------------------------------------------------------------
// GEMM: pre[M,N] = A[M,K] @ W[N,K]^T + bih[N] + bhh[N]
// M = 16384, N = 2048, K = 512. 128x128 tile, 8x8/thread, double-buffered,
// f32x2 accumulate (paired over output columns).
// ---------------------------------------------------------------------------
__global__ __launch_bounds__(256) void gemm_pre_kernel(
    const float* __restrict__ A,
    const float* __restrict__ W,
    const float* __restrict__ bih,
    const float* __restrict__ bhh,
    float* __restrict__ C)
{
    const int K = I_DIM;      // 512
    const int N = G_DIM;      // 2048

    __shared__ float As[2][8][128];
    __shared__ float Bs[2][8][128];

    const int bm = blockIdx.y * 128;
    const int bn = blockIdx.x * 128;
    const int tid = threadIdx.x;
    const int tx = tid & 15;
    const int ty = tid >> 4;

    u64 acc2[8][4];
#pragma unroll
    for (int i = 0; i < 8; i++)
#pragma unroll
        for (int jp = 0; jp < 4; jp++) acc2[i][jp] = 0ull;

    const int lr = tid >> 1;            // 0..127
    const int lc = (tid & 1) * 4;       // 0 or 4
    const float* Aptr = A + (size_t)(bm + lr) * K + lc;
    const float* Wptr = W + (size_t)(bn + lr) * K + lc;

    // prologue: load k-block 0 into buffer 0
    float4 av = *(const float4*)(Aptr);
    float4 wv = *(const float4*)(Wptr);
    As[0][lc + 0][lr] = av.x; As[0][lc + 1][lr] = av.y;
    As[0][lc + 2][lr] = av.z; As[0][lc + 3][lr] = av.w;
    Bs[0][lc + 0][lr] = wv.x; Bs[0][lc + 1][lr] = wv.y;
    Bs[0][lc + 2][lr] = wv.z; Bs[0][lc + 3][lr] = wv.w;
    __syncthreads();

    for (int kt = 0; kt < 64; kt++) {
        const int cur = kt & 1;
        if (kt < 63) {
            av = *(const float4*)(Aptr + (kt + 1) * 8);
            wv = *(const float4*)(Wptr + (kt + 1) * 8);
        }
#pragma unroll
        for (int kk = 0; kk < 8; kk++) {
            float a[8];
            *(float4*)(a)     = *(const float4*)&As[cur][kk][ty * 8];
            *(float4*)(a + 4) = *(const float4*)&As[cur][kk][ty * 8 + 4];
            const ulonglong2* bp = (const ulonglong2*)&Bs[cur][kk][tx * 8];
            ulonglong2 q0 = bp[0], q1 = bp[1];
            u64 b2[4] = { q0.x, q0.y, q1.x, q1.y };
#pragma unroll
            for (int i = 0; i < 8; i++) {
                u64 a2 = fsplat(a[i]);
#pragma unroll
                for (int jp = 0; jp < 4; jp++)
                    acc2[i][jp] = ffma2(a2, b2[jp], acc2[i][jp]);
            }
        }
        if (kt < 63) {
            const int nxt = cur ^ 1;
            As[nxt][lc + 0][lr] = av.x; As[nxt][lc + 1][lr] = av.y;
            As[nxt][lc + 2][lr] = av.z; As[nxt][lc + 3][lr] = av.w;
            Bs[nxt][lc + 0][lr] = wv.x; Bs[nxt][lc + 1][lr] = wv.y;
            Bs[nxt][lc + 2][lr] = wv.z; Bs[nxt][lc + 3][lr] = wv.w;
        }
        __syncthreads();
    }

    float bias[8];
#pragma unroll
    for (int j = 0; j < 8; j++) {
        int col = bn + tx * 8 + j;
        bias[j] = bih[col] + bhh[col];
    }
#pragma unroll
    for (int i = 0; i < 8; i++) {
        int row = bm + ty * 8 + i;
        float* cp = C + (size_t)row * N + bn + tx * 8;
        float o[8];
#pragma unroll
        for (int jp = 0; jp < 4; jp++) {
            float2 v = funpack(acc2[i][jp]);
            o[2 * jp]     = v.x + bias[2 * jp];
            o[2 * jp + 1] = v.y + bias[2 * jp + 1];
        }
        *(float4*)(cp)     = make_float4(o[0], o[1], o[2], o[3]);
        *(float4*)(cp + 4) = make_float4(o[4], o[5], o[6], o[7]);
    }
}

// ---------------------------------------------------------------------------
// Persistent LSTM recurrence, one layer. 128 CTAs x 512 threads.
// CTA bx owns h-units j0..j0+3 (16 gate columns). 16 warps = 16-way k-split:
// warp kq computes ALL 16 columns over k in [kq*32, kq*32+32). Each h LDS.128
// feeds 32 MACs (16 f32x2). Partials reduced through smem, pointwise by
// 128 threads, 2-level grid barrier per step.
// ---------------------------------------------------------------------------
__global__ __launch_bounds__(512, 1) void lstm_recur_kernel(
    const float* __restrict__ pre,     // [T, B, 4H]
    const float* __restrict__ whh,     // [4H, H]
    float* __restrict__ out,           // [6, L, T, B, H]
    int layer)
{
    extern __shared__ float4 dsm4[];
    float4* sh4 = dsm4;                         // [32][129] float4
    float4* sW4 = dsm4 + 32 * 129;              // [16][128] float4
    float*  sg  = (float*)(sW4 + 16 * 128);     // [16][32*17]
    float*  sc  = sg + 16 * 544;                // [128]
    __shared__ unsigned sBase;

    const int tid = threadIdx.x;
    const int bx  = blockIdx.x;
    const int j0  = bx * 4;

    float* out_h = out + (size_t)0 * 2 * S_TBH + (size_t)layer * S_TBH;
    float* out_c = out + (size_t)1 * 2 * S_TBH + (size_t)layer * S_TBH;
    float* out_i = out + (size_t)2 * 2 * S_TBH + (size_t)layer * S_TBH;
    float* out_f = out + (size_t)3 * 2 * S_TBH + (size_t)layer * S_TBH;
    float* out_g = out + (size_t)4 * 2 * S_TBH + (size_t)layer * S_TBH;
    float* out_o = out + (size_t)5 * 2 * S_TBH + (size_t)layer * S_TBH;

    if (tid == 0) sBase = *(volatile unsigned*)&gGen;

    // Whh slice: 16 rows (cidx = gate*4+jl -> row gate*512+j0+jl), K=512
    const float4* whh4 = (const float4*)whh;
#pragma unroll
    for (int i = 0; i < 4; i++) {
        int f = tid + i * 512;              // 0..2047
        int cidx = f >> 7, k4 = f & 127;
        int gate = cidx >> 2, jl = cidx & 3;
        int row = gate * 512 + j0 + jl;
        sW4[cidx * 128 + k4] = whh4[(size_t)row * 128 + k4];
    }
    if (tid < 128) sc[tid] = 0.f;

    const int w  = tid >> 5;
    const int b  = tid & 31;
    const int kq = w;                       // k-slice index 0..15
    const float* preb = pre + (size_t)b * G_DIM + j0;

    // prefetch pre for t=0 (only warp 0 folds pre into its partial)
    float4 p0, p1, p2, p3;
    if (kq == 0) {
        p0 = *(const float4*)(preb + 0 * 512);
        p1 = *(const float4*)(preb + 1 * 512);
        p2 = *(const float4*)(preb + 2 * 512);
        p3 = *(const float4*)(preb + 3 * 512);
    }

    for (int t = 0; t < T_DIM; t++) {
        // stage h_{t-1}
        if (t == 0) {
#pragma unroll
            for (int i = 0; i < 8; i++) {
                int f = tid + i * 512;      // 0..4095
                sh4[(f >> 7) * 129 + (f & 127)] = make_float4(0.f, 0.f, 0.f, 0.f);
            }
        } else {
            const float4* hsrc = (const float4*)(out_h + (size_t)(t - 1) * (B_DIM * H_DIM));
#pragma unroll
            for (int i = 0; i < 8; i++) {
                int f = tid + i * 512;
                sh4[(f >> 7) * 129 + (f & 127)] = hsrc[f];
            }
        }
        __syncthreads();

        u64 acc2[16];
        if (kq == 0) {
            acc2[0]  = fpack(p0.x, 0.f); acc2[1]  = fpack(p0.y, 0.f);
            acc2[2]  = fpack(p0.z, 0.f); acc2[3]  = fpack(p0.w, 0.f);
            acc2[4]  = fpack(p1.x, 0.f); acc2[5]  = fpack(p1.y, 0.f);
            acc2[6]  = fpack(p1.z, 0.f); acc2[7]  = fpack(p1.w, 0.f);
            acc2[8]  = fpack(p2.x, 0.f); acc2[9]  = fpack(p2.y, 0.f);
            acc2[10] = fpack(p2.z, 0.f); acc2[11] = fpack(p2.w, 0.f);
            acc2[12] = fpack(p3.x, 0.f); acc2[13] = fpack(p3.y, 0.f);
            acc2[14] = fpack(p3.z, 0.f); acc2[15] = fpack(p3.w, 0.f);
        } else {
#pragma unroll
            for (int c = 0; c < 16; c++) acc2[c] = 0ull;
        }

        const ulonglong2* hrow = (const ulonglong2*)(sh4 + b * 129 + kq * 8);
#pragma unroll 4
        for (int kk = 0; kk < 8; kk++) {
            ulonglong2 hv = hrow[kk];
#pragma unroll
            for (int c = 0; c < 16; c++) {
                ulonglong2 wv = *((const ulonglong2*)(sW4 + c * 128 + kq * 8) + kk);
                acc2[c] = ffma2(hv.x, wv.x, acc2[c]);
                acc2[c] = ffma2(hv.y, wv.y, acc2[c]);
            }
        }

        // prefetch pre for t+1 (hidden under reduction + barrier)
        if (kq == 0 && t + 1 < T_DIM) {
            const float* pn = preb + (size_t)(t + 1) * (B_DIM * G_DIM);
            p0 = *(const float4*)(pn + 0);
            p1 = *(const float4*)(pn + 512);
            p2 = *(const float4*)(pn + 1024);
            p3 = *(const float4*)(pn + 1536);
        }

        float* sgw = sg + kq * 544 + b * 17;
#pragma unroll
        for (int c = 0; c < 16; c++) {
            float2 v = funpack(acc2[c]);
            sgw[c] = v.x + v.y;
        }
        __syncthreads();

        if (tid < 128) {
            int eb = tid >> 2, jl = tid & 3;
            float xi = 0.f, xf = 0.f, xg = 0.f, xo = 0.f;
#pragma unroll
            for (int q = 0; q < 16; q++) {
                const float* s = sg + q * 544 + eb * 17 + jl;
                xi += s[0]; xf += s[4]; xg += s[8]; xo += s[12];
            }
            float it = 1.f / (1.f + __expf(-xi));
            float ft = 1.f / (1.f + __expf(-xf));
            float gt = tanhf(xg);
            float ot = 1.f / (1.f + __expf(-xo));
            float cold = sc[tid];
            float cnew = fmaf(ft, cold, it * gt);
            float hnew = ot * tanhf(cnew);
            sc[tid] = cnew;
            size_t idx = (size_t)t * (B_DIM * H_DIM) + eb * H_DIM + j0 + jl;
            out_h[idx] = hnew;
            out_c[idx] = cnew;
            out_i[idx] = it;
            out_f[idx] = ft;
            out_g[idx] = gt;
            out_o[idx] = ot;
        }

        if (t < T_DIM - 1) {
            __syncthreads();
            if (tid == 0) {
                __threadfence();
                unsigned v = atomicAdd(&gSub[(bx & 7) * 32], 1u) + 1u;
                if ((v & 15u) == 0u) {                    // 16 CTAs per sub
                    unsigned m = atomicAdd(&gMaster, 1u) + 1u;
                    if ((m & 7u) == 0u)                   // 8 subs
                        atomicAdd(&gGen, 1u);
                }
                unsigned target = sBase + (unsigned)(t + 1);
                unsigned g;
                do { g = *(volatile unsigned*)&gGen; } while ((int)(g - target) < 0);
                __threadfence();
            }
            __syncthreads();
        }
    }
}

// ---------------------------------------------------------------------------
extern "C" void kernel_launch(void* const* d_in, const int* in_sizes, int n_in,
                              void* d_out, int out_size)
{
    (void)in_sizes; (void)n_in; (void)out_size;
    const float* x    = (const float*)d_in[0];   // [T, B, I]
    const float* w_ih = (const float*)d_in[1];   // [L, 4H, I]
    const float* w_hh = (const float*)d_in[2];   // [L, 4H, H]
    const float* b_ih = (const float*)d_in[3];   // [L, 4H]
    const float* b_hh = (const float*)d_in[4];   // [L, 4H]
    float* out = (float*)d_out;                  // [6, L, T, B, H]

    float* pre;
    cudaGetSymbolAddress((void**)&pre, g_pre);

    const size_t recur_smem =
        (size_t)(32 * 129 + 16 * 128) * sizeof(float4) +   // h tile + W tile
        (size_t)(16 * 544 + 128) * sizeof(float);          // partials + c state
    cudaFuncSetAttribute(lstm_recur_kernel,
                         cudaFuncAttributeMaxDynamicSharedMemorySize,
                         (int)recur_smem);

    dim3 ggrid(G_DIM / 128, (T_DIM * B_DIM) / 128);   // 16 x 128

    // Layer 0
    gemm_pre_kernel<<<ggrid, 256>>>(x, w_ih, b_ih, b_hh, pre);
    lstm_recur_kernel<<<128, 512, recur_smem>>>(pre, w_hh, out, 0);

    // Layer 1: input is layer-0 h (out region q=0, l=0)
    const float* x1 = out;
    gemm_pre_kernel<<<ggrid, 256>>>(x1,
                                    w_ih + (size_t)G_DIM * I_DIM,
                                    b_ih + G_DIM,
                                    b_hh + G_DIM,
                                    pre);
    lstm_recur_kernel<<<128, 512, recur_smem>>>(pre,
                                                w_hh + (size_t)G_DIM * H_DIM,
                                                out, 1);
}